// round 1
// baseline (speedup 1.0000x reference)
#include <cuda_runtime.h>
#include <cuda_bf16.h>

// Shapes (fixed by the problem)
#define B  8
#define C  256
#define HW 65536            // 256*256
#define HW4 16384           // HW / 4 (float4 count per (b,c) plane)

// Scratch for the per-(b,c) scale factor (1 + softmax weight).
__device__ float g_scale[B * C];

// ---------------------------------------------------------------------------
// Kernel 1: MLP gate + softmax. One block per batch row, 256 threads (one per
// channel). Work is tiny (2 x 256x256 matvecs per batch) — latency only.
// ---------------------------------------------------------------------------
__global__ void gate_kernel(const float* __restrict__ semantic,
                            const float* __restrict__ W1,
                            const float* __restrict__ b1,
                            const float* __restrict__ W2,
                            const float* __restrict__ b2) {
    const int b = blockIdx.x;     // 0..7
    const int c = threadIdx.x;    // 0..255

    __shared__ float s_sem[C];
    __shared__ float s_h[C];
    __shared__ float red[C];

    s_sem[c] = semantic[b * C + c];
    __syncthreads();

    // h[c] = leaky_relu(semantic . W1[c,:] + b1[c])
    float acc = b1[c];
    const float* w1row = W1 + c * C;
    #pragma unroll 8
    for (int k = 0; k < C; ++k)
        acc = fmaf(s_sem[k], __ldg(w1row + k), acc);
    float h = acc > 0.0f ? acc : 0.1f * acc;
    s_h[c] = h;
    __syncthreads();

    // logits[c] = h . W2[c,:] + b2[c]
    float logit = b2[c];
    const float* w2row = W2 + c * C;
    #pragma unroll 8
    for (int k = 0; k < C; ++k)
        logit = fmaf(s_h[k], __ldg(w2row + k), logit);

    // softmax over the 256 channels (block reduction)
    red[c] = logit;
    __syncthreads();
    #pragma unroll
    for (int s = 128; s > 0; s >>= 1) {
        if (c < s) red[c] = fmaxf(red[c], red[c + s]);
        __syncthreads();
    }
    const float m = red[0];
    __syncthreads();

    const float e = __expf(logit - m);
    red[c] = e;
    __syncthreads();
    #pragma unroll
    for (int s = 128; s > 0; s >>= 1) {
        if (c < s) red[c] += red[c + s];
        __syncthreads();
    }
    const float denom = red[0];

    g_scale[b * C + c] = 1.0f + e / denom;
}

// ---------------------------------------------------------------------------
// Kernel 2: y = x * scale[plane], streaming float4. grid = (64, B*C).
// Each block handles 256 float4 of one (b,c) plane; each thread one float4.
// Pure HBM stream: 512 MiB read + 512 MiB write.
// ---------------------------------------------------------------------------
__global__ void __launch_bounds__(256) scale_kernel(const float4* __restrict__ x,
                                                    float4* __restrict__ y) {
    const int plane = blockIdx.y;                       // 0 .. B*C-1
    const float s = __ldg(&g_scale[plane]);
    const size_t idx = (size_t)plane * HW4 + (size_t)blockIdx.x * blockDim.x + threadIdx.x;
    float4 v = x[idx];
    v.x *= s; v.y *= s; v.z *= s; v.w *= s;
    y[idx] = v;
}

extern "C" void kernel_launch(void* const* d_in, const int* in_sizes, int n_in,
                              void* d_out, int out_size) {
    const float* x        = (const float*)d_in[0];
    const float* semantic = (const float*)d_in[1];
    const float* W1       = (const float*)d_in[2];
    const float* b1       = (const float*)d_in[3];
    const float* W2       = (const float*)d_in[4];
    const float* b2       = (const float*)d_in[5];
    float* out = (float*)d_out;

    gate_kernel<<<B, C>>>(semantic, W1, b1, W2, b2);

    dim3 grid(HW4 / 256, B * C);
    scale_kernel<<<grid, 256>>>((const float4*)x, (float4*)out);
}

// round 2
// speedup vs baseline: 1.3917x; 1.3917x over previous
#include <cuda_runtime.h>
#include <cuda_bf16.h>

#define B   8
#define C   256
#define HW4 16384   // (256*256)/4 float4 per (b,c) plane

// Scratch (no allocation allowed -> __device__ globals)
__device__ float g_h[B * C];        // hidden layer
__device__ float g_logits[B * C];   // logits
__device__ float g_scale[B * C];    // 1 + softmax weight

// ---------------------------------------------------------------------------
// Warp-per-output matvec: out[b,c] = act( in[b,:] . W[c,:] + bias[c] )
// grid = 256 blocks x 256 threads = 2048 warps = B*C outputs.
// Lanes read the weight row as coalesced float4 (64 float4 -> 2 per lane).
// ---------------------------------------------------------------------------
template <bool LEAKY>
__global__ void __launch_bounds__(256) matvec_kernel(const float* __restrict__ in,
                                                     const float* __restrict__ W,
                                                     const float* __restrict__ bias,
                                                     float* __restrict__ out) {
    const int warp = (blockIdx.x * blockDim.x + threadIdx.x) >> 5; // 0..2047
    const int lane = threadIdx.x & 31;
    const int b = warp >> 8;        // 0..7
    const int c = warp & 255;       // 0..255

    const float4* __restrict__ w4 = (const float4*)(W + c * C);
    const float4* __restrict__ i4 = (const float4*)(in + b * C);

    float4 wa = __ldg(w4 + lane);
    float4 wb = __ldg(w4 + lane + 32);
    float4 ia = __ldg(i4 + lane);
    float4 ib = __ldg(i4 + lane + 32);

    float p = wa.x * ia.x + wa.y * ia.y + wa.z * ia.z + wa.w * ia.w
            + wb.x * ib.x + wb.y * ib.y + wb.z * ib.z + wb.w * ib.w;

    #pragma unroll
    for (int s = 16; s > 0; s >>= 1)
        p += __shfl_xor_sync(0xffffffffu, p, s);

    if (lane == 0) {
        float r = p + __ldg(bias + c);
        if (LEAKY) r = r > 0.0f ? r : 0.1f * r;
        out[b * C + c] = r;
    }
}

// ---------------------------------------------------------------------------
// Softmax over channels per batch row -> g_scale = 1 + softmax(logits)
// 8 blocks x 256 threads. Tiny; logits live in L2.
// ---------------------------------------------------------------------------
__global__ void softmax_kernel() {
    const int b = blockIdx.x;
    const int c = threadIdx.x;
    __shared__ float red[C];

    const float logit = g_logits[b * C + c];
    red[c] = logit;
    __syncthreads();
    #pragma unroll
    for (int s = 128; s > 0; s >>= 1) {
        if (c < s) red[c] = fmaxf(red[c], red[c + s]);
        __syncthreads();
    }
    const float m = red[0];
    __syncthreads();

    const float e = __expf(logit - m);
    red[c] = e;
    __syncthreads();
    #pragma unroll
    for (int s = 128; s > 0; s >>= 1) {
        if (c < s) red[c] += red[c + s];
        __syncthreads();
    }
    g_scale[b * C + c] = 1.0f + e / red[0];
}

// ---------------------------------------------------------------------------
// y = x * scale[plane], streaming float4, grid (64, B*C). DRAM-bound.
// __ldcs/__stcs: x and y are touched exactly once -> evict-first.
// ---------------------------------------------------------------------------
__global__ void __launch_bounds__(256) scale_kernel(const float4* __restrict__ x,
                                                    float4* __restrict__ y) {
    const int plane = blockIdx.y;
    const float s = __ldg(&g_scale[plane]);
    const size_t idx = (size_t)plane * HW4 + (size_t)blockIdx.x * blockDim.x + threadIdx.x;
    float4 v = __ldcs(x + idx);
    v.x *= s; v.y *= s; v.z *= s; v.w *= s;
    __stcs(y + idx, v);
}

extern "C" void kernel_launch(void* const* d_in, const int* in_sizes, int n_in,
                              void* d_out, int out_size) {
    const float* x        = (const float*)d_in[0];
    const float* semantic = (const float*)d_in[1];
    const float* W1       = (const float*)d_in[2];
    const float* b1       = (const float*)d_in[3];
    const float* W2       = (const float*)d_in[4];
    const float* b2       = (const float*)d_in[5];
    float* out = (float*)d_out;

    float* g_h_ptr, *g_logits_ptr;
    cudaGetSymbolAddress((void**)&g_h_ptr, g_h);
    cudaGetSymbolAddress((void**)&g_logits_ptr, g_logits);

    matvec_kernel<true ><<<256, 256>>>(semantic, W1, b1, g_h_ptr);
    matvec_kernel<false><<<256, 256>>>(g_h_ptr, W2, b2, g_logits_ptr);
    softmax_kernel<<<B, C>>>();

    dim3 grid(HW4 / 256, B * C);
    scale_kernel<<<grid, 256>>>((const float4*)x, (float4*)out);
}